// round 1
// baseline (speedup 1.0000x reference)
#include <cuda_runtime.h>
#include <math.h>

// Problem constants
constexpr int D_MODEL = 1024;
constexpr int SEQ     = 2048;
constexpr int BATCH   = 2;
constexpr int NH      = 16;
constexpr int DK      = 64;     // D_MODEL / NH
constexpr int DFF     = 4096;
constexpr int ROWS    = BATCH * SEQ;           // 4096
constexpr float EPS   = 1e-5f;
constexpr long long OUT_ELEMS  = (long long)ROWS * D_MODEL;              // 4,194,304
constexpr long long ATTN_ELEMS = (long long)BATCH * NH * SEQ * SEQ;      // 134,217,728

// Scratch (device globals — no allocations allowed)
__device__ float g_Q  [ROWS * D_MODEL];
__device__ float g_Kp [ROWS * D_MODEL];
__device__ float g_V  [ROWS * D_MODEL];
__device__ float g_ctx[ROWS * D_MODEL];
__device__ float g_t1 [ROWS * D_MODEL];
__device__ float g_h  [ROWS * D_MODEL];
__device__ float g_ff [ROWS * DFF];
__device__ float g_attn_fallback[BATCH * NH * SEQ * SEQ];  // used only if attn isn't part of d_out

// ---------------------------------------------------------------------------
// Tiled fp32 GEMM body: C[m0:m0+64, n0:n0+64] = scale * A @ B (+bias)(+gelu)
// A is MxK row-major (lda). If BT=false: B is KxN row-major (ldb).
// If BT=true : B is NxK row-major (ldb)  (i.e. C = A @ B^T).
// 256 threads, BK=16, each thread owns a 4x4 micro-tile.
// ---------------------------------------------------------------------------
template<bool BT>
__device__ __forceinline__ void gemm_body(
    const float* __restrict__ A, int lda,
    const float* __restrict__ B, int ldb,
    const float* __restrict__ bias,
    float* __restrict__ C, int ldc,
    int K, int m0, int n0, float scale, int act)
{
    __shared__ float As[16][64];
    __shared__ float Bs[16][64];
    const int t  = threadIdx.x;
    const int tx = t & 15;      // 0..15 -> 4 output cols each
    const int ty = t >> 4;      // 0..15 -> 4 output rows each

    float acc[4][4] = {};

    for (int k0 = 0; k0 < K; k0 += 16) {
        // Load A tile 64x16 (transposed into As[k][m]) — float4 per thread
        {
            int r = t >> 2;                // 0..63
            int c = (t & 3) << 2;          // 0,4,8,12
            float4 v = *reinterpret_cast<const float4*>(
                &A[(size_t)(m0 + r) * lda + k0 + c]);
            As[c + 0][r] = v.x; As[c + 1][r] = v.y;
            As[c + 2][r] = v.z; As[c + 3][r] = v.w;
        }
        if (!BT) {
            // B tile 16x64 direct
            int r = t >> 4;                // 0..15 (k)
            int c = (t & 15) << 2;         // 0..60 (n)
            float4 v = *reinterpret_cast<const float4*>(
                &B[(size_t)(k0 + r) * ldb + n0 + c]);
            *reinterpret_cast<float4*>(&Bs[r][c]) = v;
        } else {
            // B tile: rows are n, cols are k -> transpose into Bs[k][n]
            int n = t >> 2;                // 0..63
            int c = (t & 3) << 2;          // 0,4,8,12 (k)
            float4 v = *reinterpret_cast<const float4*>(
                &B[(size_t)(n0 + n) * ldb + k0 + c]);
            Bs[c + 0][n] = v.x; Bs[c + 1][n] = v.y;
            Bs[c + 2][n] = v.z; Bs[c + 3][n] = v.w;
        }
        __syncthreads();

        #pragma unroll
        for (int k = 0; k < 16; k++) {
            float a[4], b[4];
            #pragma unroll
            for (int i = 0; i < 4; i++) a[i] = As[k][ty * 4 + i];
            #pragma unroll
            for (int j = 0; j < 4; j++) b[j] = Bs[k][tx * 4 + j];
            #pragma unroll
            for (int i = 0; i < 4; i++)
                #pragma unroll
                for (int j = 0; j < 4; j++)
                    acc[i][j] = fmaf(a[i], b[j], acc[i][j]);
        }
        __syncthreads();
    }

    #pragma unroll
    for (int i = 0; i < 4; i++) {
        int m = m0 + ty * 4 + i;
        #pragma unroll
        for (int j = 0; j < 4; j++) {
            int n = n0 + tx * 4 + j;
            float v = acc[i][j] * scale;
            if (bias) v += bias[n];
            if (act == 1) v = v * normcdff(v);   // exact GELU: x * Phi(x)
            C[(size_t)m * ldc + n] = v;
        }
    }
}

// Generic NN gemm: C = A@B + bias, optional GELU
__global__ void k_gemm(const float* __restrict__ A, int lda,
                       const float* __restrict__ B, int ldb,
                       const float* __restrict__ bias,
                       float* __restrict__ C, int ldc, int K, int act)
{
    gemm_body<false>(A, lda, B, ldb, bias, C, ldc, K,
                     blockIdx.y * 64, blockIdx.x * 64, 1.0f, act);
}

// scores[z] = (Q_z @ K_z^T) / sqrt(64), z = b*16+h, each SEQ x SEQ
__global__ void k_scores(const float* __restrict__ Q,
                         const float* __restrict__ Kt,
                         float* __restrict__ S)
{
    int z = blockIdx.z, b = z >> 4, h = z & 15;
    const float* Ap = Q  + ((size_t)b * SEQ) * D_MODEL + (size_t)h * DK;
    const float* Bp = Kt + ((size_t)b * SEQ) * D_MODEL + (size_t)h * DK;
    float* Cp = S + (size_t)z * SEQ * SEQ;
    gemm_body<true>(Ap, D_MODEL, Bp, D_MODEL, nullptr, Cp, SEQ, DK,
                    blockIdx.y * 64, blockIdx.x * 64, 0.125f, 0);
}

// ctx[z] = attn_z @ V_z   (M=SEQ, N=64, K=SEQ), written head-interleaved
__global__ void k_ctx(const float* __restrict__ S,
                      const float* __restrict__ V,
                      float* __restrict__ Cx)
{
    int z = blockIdx.z, b = z >> 4, h = z & 15;
    const float* Ap = S + (size_t)z * SEQ * SEQ;
    const float* Bp = V  + ((size_t)b * SEQ) * D_MODEL + (size_t)h * DK;
    float* Cp       = Cx + ((size_t)b * SEQ) * D_MODEL + (size_t)h * DK;
    gemm_body<false>(Ap, SEQ, Bp, D_MODEL, nullptr, Cp, D_MODEL, SEQ,
                     blockIdx.y * 64, blockIdx.x * 64, 1.0f, 0);
}

// In-place softmax over rows of length SEQ. One block (256 thr) per row.
__global__ void k_softmax(float* __restrict__ S)
{
    float* p = S + (size_t)blockIdx.x * SEQ;
    int t = threadIdx.x;
    __shared__ float red[256];

    float m = -3.0e38f;
    for (int i = t; i < SEQ; i += 256) m = fmaxf(m, p[i]);
    red[t] = m; __syncthreads();
    for (int s = 128; s > 0; s >>= 1) {
        if (t < s) red[t] = fmaxf(red[t], red[t + s]);
        __syncthreads();
    }
    float rm = red[0];
    __syncthreads();

    float sum = 0.0f;
    for (int i = t; i < SEQ; i += 256) {
        float e = __expf(p[i] - rm);
        p[i] = e;
        sum += e;
    }
    red[t] = sum; __syncthreads();
    for (int s = 128; s > 0; s >>= 1) {
        if (t < s) red[t] += red[t + s];
        __syncthreads();
    }
    float inv = 1.0f / red[0];
    for (int i = t; i < SEQ; i += 256) p[i] *= inv;
}

// out_row = LayerNorm(r_row + y_row) * g + b.  One block (256 thr) per row.
__global__ void k_ln(const float* __restrict__ r, const float* __restrict__ y,
                     const float* __restrict__ g, const float* __restrict__ bta,
                     float* __restrict__ out)
{
    size_t row = blockIdx.x;
    const float* rp = r + row * D_MODEL;
    const float* yp = y + row * D_MODEL;
    float* op = out + row * D_MODEL;
    int t = threadIdx.x;

    __shared__ float s1[256], s2[256];
    float v[4];
    float sum = 0.0f, sq = 0.0f;
    #pragma unroll
    for (int i = 0; i < 4; i++) {
        int c = t + i * 256;
        float x = rp[c] + yp[c];
        v[i] = x; sum += x; sq += x * x;
    }
    s1[t] = sum; s2[t] = sq; __syncthreads();
    for (int s = 128; s > 0; s >>= 1) {
        if (t < s) { s1[t] += s1[t + s]; s2[t] += s2[t + s]; }
        __syncthreads();
    }
    float mu  = s1[0] * (1.0f / D_MODEL);
    float var = s2[0] * (1.0f / D_MODEL) - mu * mu;
    float inv = rsqrtf(var + EPS);
    #pragma unroll
    for (int i = 0; i < 4; i++) {
        int c = t + i * 256;
        op[c] = (v[i] - mu) * inv * g[c] + bta[c];
    }
}

extern "C" void kernel_launch(void* const* d_in, const int* in_sizes, int n_in,
                              void* d_out, int out_size)
{
    const float* x   = (const float*)d_in[0];
    const float* Wq  = (const float*)d_in[1];
    const float* bq  = (const float*)d_in[2];
    const float* Wk  = (const float*)d_in[3];
    const float* bk  = (const float*)d_in[4];
    const float* Wv  = (const float*)d_in[5];
    const float* bv  = (const float*)d_in[6];
    const float* Wo  = (const float*)d_in[7];
    const float* bo  = (const float*)d_in[8];
    const float* g1  = (const float*)d_in[9];
    const float* b1  = (const float*)d_in[10];
    const float* W1  = (const float*)d_in[11];
    const float* bf1 = (const float*)d_in[12];
    const float* W2  = (const float*)d_in[13];
    const float* bf2 = (const float*)d_in[14];
    const float* g2  = (const float*)d_in[15];
    const float* b2  = (const float*)d_in[16];
    float* out = (float*)d_out;

    float *Qb, *Kb, *Vb, *Cx, *T1, *H, *FF, *ATf;
    cudaGetSymbolAddress((void**)&Qb,  g_Q);
    cudaGetSymbolAddress((void**)&Kb,  g_Kp);
    cudaGetSymbolAddress((void**)&Vb,  g_V);
    cudaGetSymbolAddress((void**)&Cx,  g_ctx);
    cudaGetSymbolAddress((void**)&T1,  g_t1);
    cudaGetSymbolAddress((void**)&H,   g_h);
    cudaGetSymbolAddress((void**)&FF,  g_ff);
    cudaGetSymbolAddress((void**)&ATf, g_attn_fallback);

    // attn is the second tuple output: write straight into d_out if it's there
    float* attn = ((long long)out_size >= OUT_ELEMS + ATTN_ELEMS)
                      ? (out + OUT_ELEMS) : ATf;

    dim3 blk(256);

    // Q/K/V projections: [4096,1024] @ [1024,1024] + bias
    dim3 gProj(D_MODEL / 64, ROWS / 64);
    k_gemm<<<gProj, blk>>>(x, D_MODEL, Wq, D_MODEL, bq, Qb, D_MODEL, D_MODEL, 0);
    k_gemm<<<gProj, blk>>>(x, D_MODEL, Wk, D_MODEL, bk, Kb, D_MODEL, D_MODEL, 0);
    k_gemm<<<gProj, blk>>>(x, D_MODEL, Wv, D_MODEL, bv, Vb, D_MODEL, D_MODEL, 0);

    // scores = QK^T / 8  (32 batched 2048x2048x64 NT gemms)
    k_scores<<<dim3(SEQ / 64, SEQ / 64, BATCH * NH), blk>>>(Qb, Kb, attn);

    // softmax in place (this IS the attn output)
    k_softmax<<<BATCH * NH * SEQ, blk>>>(attn);

    // ctx = attn @ V   (32 batched 2048x64x2048 gemms)
    k_ctx<<<dim3(DK / 64, SEQ / 64, BATCH * NH), blk>>>(attn, Vb, Cx);

    // attn_out = ctx @ Wo + bo
    k_gemm<<<gProj, blk>>>(Cx, D_MODEL, Wo, D_MODEL, bo, T1, D_MODEL, D_MODEL, 0);

    // h = LN(x + attn_out)
    k_ln<<<ROWS, blk>>>(x, T1, g1, b1, H);

    // ff = gelu(h @ W1 + bf1)
    k_gemm<<<dim3(DFF / 64, ROWS / 64), blk>>>(H, D_MODEL, W1, DFF, bf1, FF, DFF, D_MODEL, 1);

    // ff2 = ff @ W2 + bf2
    k_gemm<<<gProj, blk>>>(FF, DFF, W2, D_MODEL, bf2, T1, D_MODEL, DFF, 0);

    // out = LN(h + ff2)
    k_ln<<<ROWS, blk>>>(H, T1, g2, b2, out);
}

// round 2
// speedup vs baseline: 1.0744x; 1.0744x over previous
#include <cuda_runtime.h>
#include <math.h>

// Problem constants
constexpr int D_MODEL = 1024;
constexpr int SEQ     = 2048;
constexpr int BATCH   = 2;
constexpr int NH      = 16;
constexpr int DK      = 64;
constexpr int DFF     = 4096;
constexpr int ROWS    = BATCH * SEQ;           // 4096
constexpr float EPS   = 1e-5f;
constexpr long long OUT_ELEMS  = (long long)ROWS * D_MODEL;
constexpr long long ATTN_ELEMS = (long long)BATCH * NH * SEQ * SEQ;

// Scratch (device globals — no allocations allowed)
__device__ float g_Q  [ROWS * D_MODEL];
__device__ float g_Kp [ROWS * D_MODEL];
__device__ float g_V  [ROWS * D_MODEL];
__device__ float g_ctx[ROWS * D_MODEL];
__device__ float g_t1 [ROWS * D_MODEL];
__device__ float g_h  [ROWS * D_MODEL];
__device__ float g_ff [ROWS * DFF];
__device__ float g_attn_fallback[BATCH * NH * SEQ * SEQ];

// ---------------------------------------------------------------------------
// Tiled fp32 GEMM body, BMxBN tile, TMxTN micro-tile per thread.
// A: MxK row-major. BT=false: B is KxN row-major; BT=true: B is NxK (C=A@B^T).
// Shared tiles stored k-major with +4 padding (keeps 16B alignment, breaks
// the stride-128 write conflicts on the transposed stores).
// ---------------------------------------------------------------------------
template<int BM, int BN, int BK, int TM, int TN, bool BT>
__device__ __forceinline__ void gemm_body(
    const float* __restrict__ A, int lda,
    const float* __restrict__ B, int ldb,
    const float* __restrict__ bias,
    float* __restrict__ C, int ldc,
    int K, int m0, int n0, float scale, int act)
{
    constexpr int NT = (BM / TM) * (BN / TN);
    constexpr int AP = BM + 4;
    constexpr int BP = BN + 4;
    __shared__ float As[BK * AP];
    __shared__ float Bs[BK * BP];

    const int t  = threadIdx.x;
    const int tx = t % (BN / TN);
    const int ty = t / (BN / TN);

    float acc[TM][TN] = {};

    for (int k0 = 0; k0 < K; k0 += BK) {
        // A tile BMxBK -> transposed As[k][m]
        #pragma unroll
        for (int i = t; i < BM * BK / 4; i += NT) {
            int r = i / (BK / 4);
            int c = (i % (BK / 4)) * 4;
            float4 v = *reinterpret_cast<const float4*>(
                &A[(size_t)(m0 + r) * lda + k0 + c]);
            As[(c + 0) * AP + r] = v.x; As[(c + 1) * AP + r] = v.y;
            As[(c + 2) * AP + r] = v.z; As[(c + 3) * AP + r] = v.w;
        }
        if (!BT) {
            // B tile BKxBN direct into Bs[k][n]
            #pragma unroll
            for (int i = t; i < BK * BN / 4; i += NT) {
                int r = i / (BN / 4);
                int c = (i % (BN / 4)) * 4;
                float4 v = *reinterpret_cast<const float4*>(
                    &B[(size_t)(k0 + r) * ldb + n0 + c]);
                *reinterpret_cast<float4*>(&Bs[r * BP + c]) = v;
            }
        } else {
            // B rows are n, cols are k -> transpose into Bs[k][n]
            #pragma unroll
            for (int i = t; i < BN * BK / 4; i += NT) {
                int n = i / (BK / 4);
                int c = (i % (BK / 4)) * 4;
                float4 v = *reinterpret_cast<const float4*>(
                    &B[(size_t)(n0 + n) * ldb + k0 + c]);
                Bs[(c + 0) * BP + n] = v.x; Bs[(c + 1) * BP + n] = v.y;
                Bs[(c + 2) * BP + n] = v.z; Bs[(c + 3) * BP + n] = v.w;
            }
        }
        __syncthreads();

        #pragma unroll
        for (int k = 0; k < BK; k++) {
            float a[TM], b[TN];
            #pragma unroll
            for (int i = 0; i < TM; i += 4)
                *reinterpret_cast<float4*>(&a[i]) =
                    *reinterpret_cast<const float4*>(&As[k * AP + ty * TM + i]);
            #pragma unroll
            for (int j = 0; j < TN; j += 4)
                *reinterpret_cast<float4*>(&b[j]) =
                    *reinterpret_cast<const float4*>(&Bs[k * BP + tx * TN + j]);
            #pragma unroll
            for (int i = 0; i < TM; i++)
                #pragma unroll
                for (int j = 0; j < TN; j++)
                    acc[i][j] = fmaf(a[i], b[j], acc[i][j]);
        }
        __syncthreads();
    }

    #pragma unroll
    for (int i = 0; i < TM; i++) {
        int m = m0 + ty * TM + i;
        #pragma unroll
        for (int j = 0; j < TN; j++) {
            int n = n0 + tx * TN + j;
            float v = acc[i][j] * scale;
            if (bias) v += bias[n];
            if (act == 1) v = v * normcdff(v);   // exact GELU
            C[(size_t)m * ldc + n] = v;
        }
    }
}

// Generic NN gemm: C = A@B + bias, optional GELU. 128x128 tile, 256 thr.
__global__ void __launch_bounds__(256, 2)
k_gemm(const float* __restrict__ A, int lda,
       const float* __restrict__ B, int ldb,
       const float* __restrict__ bias,
       float* __restrict__ C, int ldc, int K, int act)
{
    gemm_body<128, 128, 16, 8, 8, false>(A, lda, B, ldb, bias, C, ldc, K,
                                         blockIdx.y * 128, blockIdx.x * 128,
                                         1.0f, act);
}

// scores[z] = (Q_z @ K_z^T) / 8
__global__ void __launch_bounds__(256, 2)
k_scores(const float* __restrict__ Q, const float* __restrict__ Kt,
         float* __restrict__ S)
{
    int z = blockIdx.z, b = z >> 4, h = z & 15;
    const float* Ap = Q  + ((size_t)b * SEQ) * D_MODEL + (size_t)h * DK;
    const float* Bp = Kt + ((size_t)b * SEQ) * D_MODEL + (size_t)h * DK;
    float* Cp = S + (size_t)z * SEQ * SEQ;
    gemm_body<128, 128, 16, 8, 8, true>(Ap, D_MODEL, Bp, D_MODEL, nullptr,
                                        Cp, SEQ, DK,
                                        blockIdx.y * 128, blockIdx.x * 128,
                                        0.125f, 0);
}

// ctx[z] = attn_z @ V_z  (M=SEQ, N=64, K=SEQ), head-interleaved output.
__global__ void __launch_bounds__(128, 4)
k_ctx(const float* __restrict__ S, const float* __restrict__ V,
      float* __restrict__ Cx)
{
    int z = blockIdx.z, b = z >> 4, h = z & 15;
    const float* Ap = S + (size_t)z * SEQ * SEQ;
    const float* Bp = V  + ((size_t)b * SEQ) * D_MODEL + (size_t)h * DK;
    float* Cp       = Cx + ((size_t)b * SEQ) * D_MODEL + (size_t)h * DK;
    gemm_body<128, 64, 16, 8, 8, false>(Ap, SEQ, Bp, D_MODEL, nullptr,
                                        Cp, D_MODEL, SEQ,
                                        blockIdx.y * 128, 0, 1.0f, 0);
}

// Single-pass register-resident softmax over rows of SEQ. 256 thr/row.
__global__ void k_softmax(float* __restrict__ S)
{
    float4* p = reinterpret_cast<float4*>(S + (size_t)blockIdx.x * SEQ);
    int t = threadIdx.x;
    int w = t >> 5, l = t & 31;
    __shared__ float red[8];

    float4 v0 = p[t], v1 = p[t + 256];

    float m = fmaxf(fmaxf(fmaxf(v0.x, v0.y), fmaxf(v0.z, v0.w)),
                    fmaxf(fmaxf(v1.x, v1.y), fmaxf(v1.z, v1.w)));
    #pragma unroll
    for (int s = 16; s > 0; s >>= 1) m = fmaxf(m, __shfl_xor_sync(~0u, m, s));
    if (l == 0) red[w] = m;
    __syncthreads();
    m = red[0];
    #pragma unroll
    for (int i = 1; i < 8; i++) m = fmaxf(m, red[i]);
    __syncthreads();

    v0.x = __expf(v0.x - m); v0.y = __expf(v0.y - m);
    v0.z = __expf(v0.z - m); v0.w = __expf(v0.w - m);
    v1.x = __expf(v1.x - m); v1.y = __expf(v1.y - m);
    v1.z = __expf(v1.z - m); v1.w = __expf(v1.w - m);

    float sum = v0.x + v0.y + v0.z + v0.w + v1.x + v1.y + v1.z + v1.w;
    #pragma unroll
    for (int s = 16; s > 0; s >>= 1) sum += __shfl_xor_sync(~0u, sum, s);
    if (l == 0) red[w] = sum;
    __syncthreads();
    sum = red[0];
    #pragma unroll
    for (int i = 1; i < 8; i++) sum += red[i];

    float inv = 1.0f / sum;
    v0.x *= inv; v0.y *= inv; v0.z *= inv; v0.w *= inv;
    v1.x *= inv; v1.y *= inv; v1.z *= inv; v1.w *= inv;
    p[t] = v0; p[t + 256] = v1;
}

// out = LayerNorm(r + y) * g + b.  One block (256 thr) per row.
__global__ void k_ln(const float* __restrict__ r, const float* __restrict__ y,
                     const float* __restrict__ g, const float* __restrict__ bta,
                     float* __restrict__ out)
{
    size_t row = blockIdx.x;
    const float* rp = r + row * D_MODEL;
    const float* yp = y + row * D_MODEL;
    float* op = out + row * D_MODEL;
    int t = threadIdx.x;

    __shared__ float s1[256], s2[256];
    float v[4];
    float sum = 0.0f, sq = 0.0f;
    #pragma unroll
    for (int i = 0; i < 4; i++) {
        int c = t + i * 256;
        float x = rp[c] + yp[c];
        v[i] = x; sum += x; sq += x * x;
    }
    s1[t] = sum; s2[t] = sq; __syncthreads();
    for (int s = 128; s > 0; s >>= 1) {
        if (t < s) { s1[t] += s1[t + s]; s2[t] += s2[t + s]; }
        __syncthreads();
    }
    float mu  = s1[0] * (1.0f / D_MODEL);
    float var = s2[0] * (1.0f / D_MODEL) - mu * mu;
    float inv = rsqrtf(var + EPS);
    #pragma unroll
    for (int i = 0; i < 4; i++) {
        int c = t + i * 256;
        op[c] = (v[i] - mu) * inv * g[c] + bta[c];
    }
}

extern "C" void kernel_launch(void* const* d_in, const int* in_sizes, int n_in,
                              void* d_out, int out_size)
{
    const float* x   = (const float*)d_in[0];
    const float* Wq  = (const float*)d_in[1];
    const float* bq  = (const float*)d_in[2];
    const float* Wk  = (const float*)d_in[3];
    const float* bk  = (const float*)d_in[4];
    const float* Wv  = (const float*)d_in[5];
    const float* bv  = (const float*)d_in[6];
    const float* Wo  = (const float*)d_in[7];
    const float* bo  = (const float*)d_in[8];
    const float* g1  = (const float*)d_in[9];
    const float* b1  = (const float*)d_in[10];
    const float* W1  = (const float*)d_in[11];
    const float* bf1 = (const float*)d_in[12];
    const float* W2  = (const float*)d_in[13];
    const float* bf2 = (const float*)d_in[14];
    const float* g2  = (const float*)d_in[15];
    const float* b2  = (const float*)d_in[16];
    float* out = (float*)d_out;

    float *Qb, *Kb, *Vb, *Cx, *T1, *H, *FF, *ATf;
    cudaGetSymbolAddress((void**)&Qb,  g_Q);
    cudaGetSymbolAddress((void**)&Kb,  g_Kp);
    cudaGetSymbolAddress((void**)&Vb,  g_V);
    cudaGetSymbolAddress((void**)&Cx,  g_ctx);
    cudaGetSymbolAddress((void**)&T1,  g_t1);
    cudaGetSymbolAddress((void**)&H,   g_h);
    cudaGetSymbolAddress((void**)&FF,  g_ff);
    cudaGetSymbolAddress((void**)&ATf, g_attn_fallback);

    float* attn = ((long long)out_size >= OUT_ELEMS + ATTN_ELEMS)
                      ? (out + OUT_ELEMS) : ATf;

    dim3 blk(256);
    dim3 gProj(D_MODEL / 128, ROWS / 128);   // (8, 32)

    // Q/K/V projections
    k_gemm<<<gProj, blk>>>(x, D_MODEL, Wq, D_MODEL, bq, Qb, D_MODEL, D_MODEL, 0);
    k_gemm<<<gProj, blk>>>(x, D_MODEL, Wk, D_MODEL, bk, Kb, D_MODEL, D_MODEL, 0);
    k_gemm<<<gProj, blk>>>(x, D_MODEL, Wv, D_MODEL, bv, Vb, D_MODEL, D_MODEL, 0);

    // scores = QK^T / 8
    k_scores<<<dim3(SEQ / 128, SEQ / 128, BATCH * NH), blk>>>(Qb, Kb, attn);

    // softmax in place (attn output)
    k_softmax<<<BATCH * NH * SEQ, blk>>>(attn);

    // ctx = attn @ V
    k_ctx<<<dim3(1, SEQ / 128, BATCH * NH), dim3(128)>>>(attn, Vb, Cx);

    // attn_out = ctx @ Wo + bo
    k_gemm<<<gProj, blk>>>(Cx, D_MODEL, Wo, D_MODEL, bo, T1, D_MODEL, D_MODEL, 0);

    // h = LN(x + attn_out)
    k_ln<<<ROWS, blk>>>(x, T1, g1, b1, H);

    // ff = gelu(h @ W1 + bf1)
    k_gemm<<<dim3(DFF / 128, ROWS / 128), blk>>>(H, D_MODEL, W1, DFF, bf1, FF, DFF, D_MODEL, 1);

    // ff2 = ff @ W2 + bf2
    k_gemm<<<gProj, blk>>>(FF, DFF, W2, D_MODEL, bf2, T1, D_MODEL, DFF, 0);

    // out = LN(h + ff2)
    k_ln<<<ROWS, blk>>>(H, T1, g2, b2, out);
}

// round 6
// speedup vs baseline: 2.7289x; 2.5399x over previous
#include <cuda_runtime.h>
#include <cuda_bf16.h>
#include <math.h>
#include <stdint.h>

typedef __nv_bfloat16 bf16;

constexpr int D_MODEL = 1024;
constexpr int SEQ     = 2048;
constexpr int BATCH   = 2;
constexpr int NH      = 16;
constexpr int DK      = 64;
constexpr int DFF     = 4096;
constexpr int ROWS    = BATCH * SEQ;     // 4096
constexpr float EPS   = 1e-5f;
constexpr long long OUT_ELEMS  = (long long)ROWS * D_MODEL;
constexpr long long ATTN_ELEMS = (long long)BATCH * NH * SEQ * SEQ;

// ---------------- device scratch ----------------
__device__ bf16 g_xhi [ROWS * D_MODEL], g_xlo [ROWS * D_MODEL];
__device__ bf16 g_wqt_hi[D_MODEL * D_MODEL], g_wqt_lo[D_MODEL * D_MODEL];
__device__ bf16 g_wkt_hi[D_MODEL * D_MODEL], g_wkt_lo[D_MODEL * D_MODEL];
__device__ bf16 g_wvt_hi[D_MODEL * D_MODEL], g_wvt_lo[D_MODEL * D_MODEL];
__device__ bf16 g_wot_hi[D_MODEL * D_MODEL], g_wot_lo[D_MODEL * D_MODEL];
__device__ bf16 g_w1t_hi[(long long)D_MODEL * DFF], g_w1t_lo[(long long)D_MODEL * DFF];
__device__ bf16 g_w2t_hi[(long long)D_MODEL * DFF], g_w2t_lo[(long long)D_MODEL * DFF];
__device__ bf16 g_Qhi [ROWS * D_MODEL], g_Qlo [ROWS * D_MODEL];
__device__ bf16 g_Khi [ROWS * D_MODEL], g_Klo [ROWS * D_MODEL];
__device__ bf16 g_Vhi [ROWS * D_MODEL], g_Vlo [ROWS * D_MODEL];
__device__ bf16 g_Ahi [ATTN_ELEMS], g_Alo [ATTN_ELEMS];
__device__ bf16 g_ctxhi[ROWS * D_MODEL], g_ctxlo[ROWS * D_MODEL];
__device__ bf16 g_hhi [ROWS * D_MODEL], g_hlo [ROWS * D_MODEL];
__device__ bf16 g_ffhi[(long long)ROWS * DFF], g_fflo[(long long)ROWS * DFF];
__device__ float g_T1[ROWS * D_MODEL];
__device__ float g_H [ROWS * D_MODEL];
__device__ float g_attn_fallback[ATTN_ELEMS];

// ---------------- PTX helpers ----------------
__device__ __forceinline__ uint32_t smem_u32(const void* p) {
    uint32_t a;
    asm("{ .reg .u64 t; cvta.to.shared.u64 t, %1; cvt.u32.u64 %0, t; }" : "=r"(a) : "l"(p));
    return a;
}
#define CP16(d, s)   asm volatile("cp.async.cg.shared.global [%0], [%1], 16;" :: "r"(d), "l"(s))
#define CP_COMMIT()  asm volatile("cp.async.commit_group;" ::: "memory")
#define CP_WAIT0()   asm volatile("cp.async.wait_group 0;" ::: "memory")
#define CP_WAIT1()   asm volatile("cp.async.wait_group 1;" ::: "memory")

#define LDSM4(r0, r1, r2, r3, a) \
    asm volatile("ldmatrix.sync.aligned.m8n8.x4.shared.b16 {%0,%1,%2,%3}, [%4];" \
                 : "=r"(r0), "=r"(r1), "=r"(r2), "=r"(r3) : "r"(a))
#define LDSM4T(r0, r1, r2, r3, a) \
    asm volatile("ldmatrix.sync.aligned.m8n8.x4.trans.shared.b16 {%0,%1,%2,%3}, [%4];" \
                 : "=r"(r0), "=r"(r1), "=r"(r2), "=r"(r3) : "r"(a))

__device__ __forceinline__ void mma_bf16(float* c, const uint32_t* a, uint32_t b0, uint32_t b1) {
    asm volatile(
        "mma.sync.aligned.m16n8k16.row.col.f32.bf16.bf16.f32 "
        "{%0,%1,%2,%3}, {%4,%5,%6,%7}, {%8,%9}, {%0,%1,%2,%3};"
        : "+f"(c[0]), "+f"(c[1]), "+f"(c[2]), "+f"(c[3])
        : "r"(a[0]), "r"(a[1]), "r"(a[2]), "r"(a[3]), "r"(b0), "r"(b1));
}

__device__ __forceinline__ void split2(float v, bf16& h, bf16& l) {
    h = __float2bfloat16(v);
    l = __float2bfloat16(v - __bfloat162float(h));
}

// ---------------------------------------------------------------------------
// Split-bf16 GEMM via mma.sync. BM=128 x BN tile, BK=32, 256 threads, 2-stage
// cp.async pipeline. A:[M][K] hi/lo. B: BKN? [K][N] (ldmatrix.trans) : [N][K].
// D = Ah*Bh + Ah*Bl + Al*Bh (fp32 accum).
// ---------------------------------------------------------------------------
template<int BN, bool BKN>
__device__ __forceinline__ void mma_gemm(
    const bf16* __restrict__ Ah, const bf16* __restrict__ Al, int lda,
    const bf16* __restrict__ Bh, const bf16* __restrict__ Bl, int ldb,
    int K, int m0, int n0,
    const float* __restrict__ bias, float scale, int act,
    float* __restrict__ Cf, int ldcf,
    bf16* __restrict__ Chi, bf16* __restrict__ Clo, int ldc2)
{
    constexpr int ASZ   = 128 * 80;                 // A tile bytes (padded 80B rows)
    constexpr int BSZ   = BKN ? 32 * 144 : BN * 80; // B tile bytes
    constexpr int STAGE = 2 * ASZ + 2 * BSZ;
    constexpr int WN_W  = BN / 32;                  // warps along n
    constexpr int WM_W  = 8 / WN_W;                 // warps along m
    constexpr int WM    = 128 / WM_W;               // rows per warp
    constexpr int M_IT  = WM / 16;

    extern __shared__ char sm[];
    const uint32_t sb = smem_u32(sm);

    const int t = threadIdx.x, lane = t & 31, w = t >> 5;
    const int wm = w / WN_W, wn = w % WN_W;

    float acc[M_IT][4][4];
    #pragma unroll
    for (int i = 0; i < M_IT; i++)
        #pragma unroll
        for (int j = 0; j < 4; j++)
            #pragma unroll
            for (int q = 0; q < 4; q++) acc[i][j][q] = 0.0f;

    const int NCH = K / 32;

    auto issue = [&](int ch, int buf) {
        uint32_t s0 = sb + buf * STAGE;
        int k0 = ch * 32;
        #pragma unroll
        for (int i = 0; i < 2; i++) {                     // A: 128 rows x 64B
            int c = i * 256 + t;
            int r = c >> 2, cb = (c & 3) << 4;
            const char* gh = (const char*)(Ah + (size_t)(m0 + r) * lda + k0) + cb;
            const char* gl = (const char*)(Al + (size_t)(m0 + r) * lda + k0) + cb;
            CP16(s0 + r * 80 + cb, gh);
            CP16(s0 + ASZ + r * 80 + cb, gl);
        }
        if (!BKN) {
            #pragma unroll
            for (int i = 0; i < BN * 4 / 256; i++) {
                int c = i * 256 + t;
                int r = c >> 2, cb = (c & 3) << 4;
                const char* gh = (const char*)(Bh + (size_t)(n0 + r) * ldb + k0) + cb;
                const char* gl = (const char*)(Bl + (size_t)(n0 + r) * ldb + k0) + cb;
                CP16(s0 + 2 * ASZ + r * 80 + cb, gh);
                CP16(s0 + 2 * ASZ + BSZ + r * 80 + cb, gl);
            }
        } else {                                          // [K][N]: 32 k-rows x 128B
            int r = t >> 3, cb = (t & 7) << 4;
            const char* gh = (const char*)(Bh + (size_t)(k0 + r) * ldb + n0) + cb;
            const char* gl = (const char*)(Bl + (size_t)(k0 + r) * ldb + n0) + cb;
            CP16(s0 + 2 * ASZ + r * 144 + cb, gh);
            CP16(s0 + 2 * ASZ + BSZ + r * 144 + cb, gl);
        }
    };

    auto compute = [&](int buf) {
        uint32_t aAh = sb + buf * STAGE;
        uint32_t aAl = aAh + ASZ;
        uint32_t aBh = aAl + ASZ;
        uint32_t aBl = aBh + BSZ;

        #pragma unroll
        for (int ks = 0; ks < 2; ks++) {
            uint32_t bh[8], bl[8];
            #pragma unroll
            for (int p = 0; p < 2; p++) {
                int nb = wn * 32 + p * 16;
                uint32_t ad;
                if (!BKN) {
                    ad = (uint32_t)((nb + ((lane >> 4) << 3) + (lane & 7)) * 80 +
                                    ks * 32 + ((lane >> 3) & 1) * 16);
                    LDSM4(bh[4*p], bh[4*p+1], bh[4*p+2], bh[4*p+3], aBh + ad);
                    LDSM4(bl[4*p], bl[4*p+1], bl[4*p+2], bl[4*p+3], aBl + ad);
                } else {
                    ad = (uint32_t)((ks * 16 + (lane & 7) + ((lane >> 3) & 1) * 8) * 144 +
                                    nb * 2 + (lane >> 4) * 16);
                    LDSM4T(bh[4*p], bh[4*p+1], bh[4*p+2], bh[4*p+3], aBh + ad);
                    LDSM4T(bl[4*p], bl[4*p+1], bl[4*p+2], bl[4*p+3], aBl + ad);
                }
            }
            uint32_t af[M_IT][4], au[M_IT];
            #pragma unroll
            for (int mi = 0; mi < M_IT; mi++) {
                au[mi] = (uint32_t)((wm * WM + mi * 16 + (lane & 15)) * 80 +
                                    ks * 32 + (lane >> 4) * 16);
                LDSM4(af[mi][0], af[mi][1], af[mi][2], af[mi][3], aAh + au[mi]);
            }
            #pragma unroll
            for (int mi = 0; mi < M_IT; mi++)
                #pragma unroll
                for (int ni = 0; ni < 4; ni++) {
                    int bi = (ni >> 1) * 4 + (ni & 1) * 2;
                    mma_bf16(acc[mi][ni], af[mi], bh[bi], bh[bi + 1]);
                }
            #pragma unroll
            for (int mi = 0; mi < M_IT; mi++)
                #pragma unroll
                for (int ni = 0; ni < 4; ni++) {
                    int bi = (ni >> 1) * 4 + (ni & 1) * 2;
                    mma_bf16(acc[mi][ni], af[mi], bl[bi], bl[bi + 1]);
                }
            #pragma unroll
            for (int mi = 0; mi < M_IT; mi++)
                LDSM4(af[mi][0], af[mi][1], af[mi][2], af[mi][3], aAl + au[mi]);
            #pragma unroll
            for (int mi = 0; mi < M_IT; mi++)
                #pragma unroll
                for (int ni = 0; ni < 4; ni++) {
                    int bi = (ni >> 1) * 4 + (ni & 1) * 2;
                    mma_bf16(acc[mi][ni], af[mi], bh[bi], bh[bi + 1]);
                }
        }
    };

    issue(0, 0);
    CP_COMMIT();
    for (int ch = 0; ch < NCH; ch++) {
        int buf = ch & 1;
        if (ch + 1 < NCH) { issue(ch + 1, buf ^ 1); CP_COMMIT(); CP_WAIT1(); }
        else              { CP_WAIT0(); }
        __syncthreads();
        compute(buf);
        __syncthreads();
    }

    // ---------------- epilogue ----------------
    const int g = lane >> 2, tq = lane & 3;
    #pragma unroll
    for (int mi = 0; mi < M_IT; mi++) {
        int mA = m0 + wm * WM + mi * 16 + g;
        #pragma unroll
        for (int ni = 0; ni < 4; ni++) {
            int n = n0 + wn * 32 + ni * 8 + 2 * tq;
            float b0v = 0.f, b1v = 0.f;
            if (bias) { b0v = bias[n]; b1v = bias[n + 1]; }
            float* c = acc[mi][ni];
            float v00 = c[0] * scale + b0v, v01 = c[1] * scale + b1v;
            float v10 = c[2] * scale + b0v, v11 = c[3] * scale + b1v;
            if (act) {
                v00 = v00 * normcdff(v00); v01 = v01 * normcdff(v01);
                v10 = v10 * normcdff(v10); v11 = v11 * normcdff(v11);
            }
            if (Cf) {
                *reinterpret_cast<float2*>(&Cf[(size_t)mA * ldcf + n])       = make_float2(v00, v01);
                *reinterpret_cast<float2*>(&Cf[(size_t)(mA + 8) * ldcf + n]) = make_float2(v10, v11);
            }
            if (Chi) {
                bf16 h0, l0, h1, l1;
                split2(v00, h0, l0); split2(v01, h1, l1);
                *reinterpret_cast<__nv_bfloat162*>(&Chi[(size_t)mA * ldc2 + n]) = __halves2bfloat162(h0, h1);
                *reinterpret_cast<__nv_bfloat162*>(&Clo[(size_t)mA * ldc2 + n]) = __halves2bfloat162(l0, l1);
                split2(v10, h0, l0); split2(v11, h1, l1);
                *reinterpret_cast<__nv_bfloat162*>(&Chi[(size_t)(mA + 8) * ldc2 + n]) = __halves2bfloat162(h0, h1);
                *reinterpret_cast<__nv_bfloat162*>(&Clo[(size_t)(mA + 8) * ldc2 + n]) = __halves2bfloat162(l0, l1);
            }
        }
    }
}

// ---------------- GEMM wrapper kernels ----------------
__global__ void __launch_bounds__(256)
k_qkv(const float* bq, const float* bk, const float* bv)
{
    int z = blockIdx.z;
    const bf16 *Bh, *Bl; const float* bias; bf16 *Chi, *Clo;
    if (z == 0)      { Bh = g_wqt_hi; Bl = g_wqt_lo; bias = bq; Chi = g_Qhi; Clo = g_Qlo; }
    else if (z == 1) { Bh = g_wkt_hi; Bl = g_wkt_lo; bias = bk; Chi = g_Khi; Clo = g_Klo; }
    else             { Bh = g_wvt_hi; Bl = g_wvt_lo; bias = bv; Chi = g_Vhi; Clo = g_Vlo; }
    mma_gemm<128, false>(g_xhi, g_xlo, D_MODEL, Bh, Bl, D_MODEL, D_MODEL,
                         blockIdx.y * 128, blockIdx.x * 128,
                         bias, 1.0f, 0, nullptr, 0, Chi, Clo, D_MODEL);
}

__global__ void __launch_bounds__(256)
k_scores(float* attn)
{
    int z = blockIdx.z, b = z >> 4, h = z & 15;
    size_t off = (size_t)b * SEQ * D_MODEL + (size_t)h * DK;
    mma_gemm<128, false>(g_Qhi + off, g_Qlo + off, D_MODEL,
                         g_Khi + off, g_Klo + off, D_MODEL, DK,
                         blockIdx.y * 128, blockIdx.x * 128,
                         nullptr, 0.125f, 0,
                         attn + (size_t)z * SEQ * SEQ, SEQ, nullptr, nullptr, 0);
}

__global__ void __launch_bounds__(256)
k_ctx()
{
    int z = blockIdx.z, b = z >> 4, h = z & 15;
    size_t offA = (size_t)z * SEQ * SEQ;
    size_t offB = (size_t)b * SEQ * D_MODEL + (size_t)h * DK;   // V rows, head cols
    size_t offC = (size_t)b * SEQ * D_MODEL + (size_t)h * DK;
    mma_gemm<64, true>(g_Ahi + offA, g_Alo + offA, SEQ,
                       g_Vhi + offB, g_Vlo + offB, D_MODEL, SEQ,
                       blockIdx.y * 128, 0,
                       nullptr, 1.0f, 0, nullptr, 0,
                       g_ctxhi + offC, g_ctxlo + offC, D_MODEL);
}

__global__ void __launch_bounds__(256)
k_wo(const float* bo)
{
    mma_gemm<128, false>(g_ctxhi, g_ctxlo, D_MODEL, g_wot_hi, g_wot_lo, D_MODEL, D_MODEL,
                         blockIdx.y * 128, blockIdx.x * 128,
                         bo, 1.0f, 0, g_T1, D_MODEL, nullptr, nullptr, 0);
}

__global__ void __launch_bounds__(256)
k_ff1(const float* bf1)
{
    mma_gemm<128, false>(g_hhi, g_hlo, D_MODEL, g_w1t_hi, g_w1t_lo, D_MODEL, D_MODEL,
                         blockIdx.y * 128, blockIdx.x * 128,
                         bf1, 1.0f, 1, nullptr, 0, g_ffhi, g_fflo, DFF);
}

__global__ void __launch_bounds__(256)
k_ff2(const float* bf2)
{
    mma_gemm<128, false>(g_ffhi, g_fflo, DFF, g_w2t_hi, g_w2t_lo, DFF, DFF,
                         blockIdx.y * 128, blockIdx.x * 128,
                         bf2, 1.0f, 0, g_T1, D_MODEL, nullptr, nullptr, 0);
}

// ---------------- conversion / pointwise kernels ----------------
__global__ void k_xsplit(const float* __restrict__ src,
                         bf16* __restrict__ hi, bf16* __restrict__ lo, long long n)
{
    long long i = (long long)blockIdx.x * blockDim.x + threadIdx.x;
    if (i < n) { bf16 h, l; split2(src[i], h, l); hi[i] = h; lo[i] = l; }
}

// W [Kd][Nd] fp32 -> Wt [Nd][Kd] bf16 hi/lo
__global__ void k_wsplit(const float* __restrict__ W,
                         bf16* __restrict__ Th, bf16* __restrict__ Tl, int Kd, int Nd)
{
    __shared__ float tile[32][33];
    int n0 = blockIdx.x * 32, k0 = blockIdx.y * 32;
    int tx = threadIdx.x, ty = threadIdx.y;      // 32 x 8
    #pragma unroll
    for (int i = 0; i < 4; i++)
        tile[ty + 8 * i][tx] = W[(size_t)(k0 + ty + 8 * i) * Nd + n0 + tx];
    __syncthreads();
    #pragma unroll
    for (int i = 0; i < 4; i++) {
        int n = n0 + ty + 8 * i, k = k0 + tx;
        bf16 h, l; split2(tile[tx][ty + 8 * i], h, l);
        Th[(size_t)n * Kd + k] = h;
        Tl[(size_t)n * Kd + k] = l;
    }
}

// softmax over rows of SEQ; fp32 in place + bf16 hi/lo split outputs
__global__ void k_softmax(float* __restrict__ S,
                          bf16* __restrict__ Shi, bf16* __restrict__ Slo)
{
    size_t row = blockIdx.x;
    float4* p = reinterpret_cast<float4*>(S + row * SEQ);
    int t = threadIdx.x, w = t >> 5, l = t & 31;
    __shared__ float red[8];

    float4 v0 = p[t], v1 = p[t + 256];
    float m = fmaxf(fmaxf(fmaxf(v0.x, v0.y), fmaxf(v0.z, v0.w)),
                    fmaxf(fmaxf(v1.x, v1.y), fmaxf(v1.z, v1.w)));
    #pragma unroll
    for (int s = 16; s > 0; s >>= 1) m = fmaxf(m, __shfl_xor_sync(~0u, m, s));
    if (l == 0) red[w] = m;
    __syncthreads();
    m = red[0];
    #pragma unroll
    for (int i = 1; i < 8; i++) m = fmaxf(m, red[i]);
    __syncthreads();

    v0.x = __expf(v0.x - m); v0.y = __expf(v0.y - m);
    v0.z = __expf(v0.z - m); v0.w = __expf(v0.w - m);
    v1.x = __expf(v1.x - m); v1.y = __expf(v1.y - m);
    v1.z = __expf(v1.z - m); v1.w = __expf(v1.w - m);
    float sum = v0.x + v0.y + v0.z + v0.w + v1.x + v1.y + v1.z + v1.w;
    #pragma unroll
    for (int s = 16; s > 0; s >>= 1) sum += __shfl_xor_sync(~0u, sum, s);
    if (l == 0) red[w] = sum;
    __syncthreads();
    sum = red[0];
    #pragma unroll
    for (int i = 1; i < 8; i++) sum += red[i];
    float inv = 1.0f / sum;
    v0.x *= inv; v0.y *= inv; v0.z *= inv; v0.w *= inv;
    v1.x *= inv; v1.y *= inv; v1.z *= inv; v1.w *= inv;
    p[t] = v0; p[t + 256] = v1;

    auto store4 = [&](size_t e0, float4 v) {
        bf16 h0, l0, h1, l1, h2, l2, h3, l3;
        split2(v.x, h0, l0); split2(v.y, h1, l1);
        split2(v.z, h2, l2); split2(v.w, h3, l3);
        __nv_bfloat162* H = reinterpret_cast<__nv_bfloat162*>(Shi + e0);
        __nv_bfloat162* L = reinterpret_cast<__nv_bfloat162*>(Slo + e0);
        H[0] = __halves2bfloat162(h0, h1); H[1] = __halves2bfloat162(h2, h3);
        L[0] = __halves2bfloat162(l0, l1); L[1] = __halves2bfloat162(l2, l3);
    };
    store4(row * SEQ + (size_t)t * 4, v0);
    store4(row * SEQ + 1024 + (size_t)t * 4, v1);
}

// out = LN(r + y)*g + b; optional fp32 and bf16 split outputs
__global__ void k_ln(const float* __restrict__ r, const float* __restrict__ y,
                     const float* __restrict__ g, const float* __restrict__ bta,
                     float* __restrict__ outf,
                     bf16* __restrict__ ohi, bf16* __restrict__ olo)
{
    size_t row = blockIdx.x;
    const float* rp = r + row * D_MODEL;
    const float* yp = y + row * D_MODEL;
    int t = threadIdx.x;
    __shared__ float s1[256], s2[256];
    float v[4]; float sum = 0, sq = 0;
    #pragma unroll
    for (int i = 0; i < 4; i++) {
        int c = t + i * 256;
        float xv = rp[c] + yp[c];
        v[i] = xv; sum += xv; sq += xv * xv;
    }
    s1[t] = sum; s2[t] = sq; __syncthreads();
    for (int s = 128; s > 0; s >>= 1) {
        if (t < s) { s1[t] += s1[t + s]; s2[t] += s2[t + s]; }
        __syncthreads();
    }
    float mu  = s1[0] * (1.0f / D_MODEL);
    float var = s2[0] * (1.0f / D_MODEL) - mu * mu;
    float inv = rsqrtf(var + EPS);
    #pragma unroll
    for (int i = 0; i < 4; i++) {
        int c = t + i * 256;
        float o = (v[i] - mu) * inv * g[c] + bta[c];
        if (outf) outf[row * D_MODEL + c] = o;
        if (ohi) { bf16 h, l; split2(o, h, l);
                   ohi[row * D_MODEL + c] = h; olo[row * D_MODEL + c] = l; }
    }
}

// ---------------- host ----------------
static inline void set_smem(const void* f, int bytes) {
    cudaFuncSetAttribute(f, cudaFuncAttributeMaxDynamicSharedMemorySize, bytes);
}

extern "C" void kernel_launch(void* const* d_in, const int* in_sizes, int n_in,
                              void* d_out, int out_size)
{
    const float* x   = (const float*)d_in[0];
    const float* Wq  = (const float*)d_in[1];
    const float* bq  = (const float*)d_in[2];
    const float* Wk  = (const float*)d_in[3];
    const float* bk  = (const float*)d_in[4];
    const float* Wv  = (const float*)d_in[5];
    const float* bv  = (const float*)d_in[6];
    const float* Wo  = (const float*)d_in[7];
    const float* bo  = (const float*)d_in[8];
    const float* g1  = (const float*)d_in[9];
    const float* b1  = (const float*)d_in[10];
    const float* W1  = (const float*)d_in[11];
    const float* bf1 = (const float*)d_in[12];
    const float* W2  = (const float*)d_in[13];
    const float* bf2 = (const float*)d_in[14];
    const float* g2  = (const float*)d_in[15];
    const float* b2  = (const float*)d_in[16];
    float* out = (float*)d_out;

    float *T1, *H, *ATf;
    bf16 *xhi, *xlo, *wqh, *wql, *wkh, *wkl, *wvh, *wvl, *woh, *wol;
    bf16 *w1h, *w1l, *w2h, *w2l, *ahi, *alo, *hhi, *hlo;
    cudaGetSymbolAddress((void**)&T1,  g_T1);
    cudaGetSymbolAddress((void**)&H,   g_H);
    cudaGetSymbolAddress((void**)&ATf, g_attn_fallback);
    cudaGetSymbolAddress((void**)&xhi, g_xhi);  cudaGetSymbolAddress((void**)&xlo, g_xlo);
    cudaGetSymbolAddress((void**)&wqh, g_wqt_hi); cudaGetSymbolAddress((void**)&wql, g_wqt_lo);
    cudaGetSymbolAddress((void**)&wkh, g_wkt_hi); cudaGetSymbolAddress((void**)&wkl, g_wkt_lo);
    cudaGetSymbolAddress((void**)&wvh, g_wvt_hi); cudaGetSymbolAddress((void**)&wvl, g_wvt_lo);
    cudaGetSymbolAddress((void**)&woh, g_wot_hi); cudaGetSymbolAddress((void**)&wol, g_wot_lo);
    cudaGetSymbolAddress((void**)&w1h, g_w1t_hi); cudaGetSymbolAddress((void**)&w1l, g_w1t_lo);
    cudaGetSymbolAddress((void**)&w2h, g_w2t_hi); cudaGetSymbolAddress((void**)&w2l, g_w2t_lo);
    cudaGetSymbolAddress((void**)&ahi, g_Ahi);  cudaGetSymbolAddress((void**)&alo, g_Alo);
    cudaGetSymbolAddress((void**)&hhi, g_hhi);  cudaGetSymbolAddress((void**)&hlo, g_hlo);

    float* attn = ((long long)out_size >= OUT_ELEMS + ATTN_ELEMS) ? (out + OUT_ELEMS) : ATf;

    // dynamic smem sizes: 2 stages * (A hi/lo + B hi/lo)
    constexpr int SM_NK = 2 * (2 * 128 * 80 + 2 * 128 * 80);   // 81920
    constexpr int SM_KN = 2 * (2 * 128 * 80 + 2 * 32 * 144);   // 59392
    set_smem((const void*)k_qkv,    SM_NK);
    set_smem((const void*)k_scores, SM_NK);
    set_smem((const void*)k_ctx,    SM_KN);
    set_smem((const void*)k_wo,     SM_NK);
    set_smem((const void*)k_ff1,    SM_NK);
    set_smem((const void*)k_ff2,    SM_NK);

    // conversions
    k_xsplit<<<(ROWS * D_MODEL + 255) / 256, 256>>>(x, xhi, xlo, (long long)ROWS * D_MODEL);
    dim3 tb(32, 8);
    k_wsplit<<<dim3(32, 32),  tb>>>(Wq, wqh, wql, D_MODEL, D_MODEL);
    k_wsplit<<<dim3(32, 32),  tb>>>(Wk, wkh, wkl, D_MODEL, D_MODEL);
    k_wsplit<<<dim3(32, 32),  tb>>>(Wv, wvh, wvl, D_MODEL, D_MODEL);
    k_wsplit<<<dim3(32, 32),  tb>>>(Wo, woh, wol, D_MODEL, D_MODEL);
    k_wsplit<<<dim3(128, 32), tb>>>(W1, w1h, w1l, D_MODEL, DFF);
    k_wsplit<<<dim3(32, 128), tb>>>(W2, w2h, w2l, DFF, D_MODEL);

    // Q/K/V projections
    k_qkv<<<dim3(D_MODEL / 128, ROWS / 128, 3), 256, SM_NK>>>(bq, bk, bv);

    // scores = QK^T / 8
    k_scores<<<dim3(SEQ / 128, SEQ / 128, BATCH * NH), 256, SM_NK>>>(attn);

    // softmax in place + bf16 splits
    k_softmax<<<BATCH * NH * SEQ, 256>>>(attn, ahi, alo);

    // ctx = attn @ V
    k_ctx<<<dim3(1, SEQ / 128, BATCH * NH), 256, SM_KN>>>();

    // attn_out = ctx @ Wo + bo
    k_wo<<<dim3(D_MODEL / 128, ROWS / 128), 256, SM_NK>>>(bo);

    // h = LN(x + attn_out)
    k_ln<<<ROWS, 256>>>(x, T1, g1, b1, H, hhi, hlo);

    // ff = gelu(h @ W1 + bf1)
    k_ff1<<<dim3(DFF / 128, ROWS / 128), 256, SM_NK>>>(bf1);

    // ff2 = ff @ W2 + bf2
    k_ff2<<<dim3(D_MODEL / 128, ROWS / 128), 256, SM_NK>>>(bf2);

    // out = LN(h + ff2)
    k_ln<<<ROWS, 256>>>(H, T1, g2, b2, out, nullptr, nullptr);
}